// round 1
// baseline (speedup 1.0000x reference)
#include <cuda_runtime.h>
#include <math.h>

// ---------------- constants ----------------
#define NROWS_COLS   128
#define PADK         68        // padded column stride (floats) -> conflict-free LDS.128
#define OFF_W0T      0
#define OFF_W1T      2176
#define OFF_W2T      4352
#define OFF_W3T      6528
#define OFF_WAT      8704
#define OFF_WBT      10880
#define OFF_WM1T     13056
#define OFF_WM2T     17408
#define OFF_WM3T     21760
#define WTOT         30464     // total weight floats in smem
#define WARP_STAGE   960       // per-warp staging floats
#define NWARP        16
#define SMEM_FLOATS  (WTOT + NWARP * WARP_STAGE)   // 45824
#define SMEM_BYTES   (SMEM_FLOATS * 4)             // 183296

__device__ float g_cst;
__device__ float g_wbuf[WTOT];

// ---------------- prep: silu normalization constant (trapz, matches numpy) -------------
__global__ void prep_cst_kernel() {
    const int   N = 20000;                 // intervals; error vs 200001-pt trapz ~1e-7 rel
    const float h = 24.0f / 20000.0f;
    float local = 0.0f;
    for (int i = threadIdx.x; i <= N; i += blockDim.x) {
        float z   = -12.0f + h * (float)i;
        float s   = z / (1.0f + __expf(-z));                       // silu(z)
        float phi = __expf(-0.5f * z * z) * 0.3989422804014327f;   // N(0,1) pdf
        float f   = s * s * phi;
        if (i == 0 || i == N) f *= 0.5f;
        local += f;
    }
    __shared__ float red[256];
    red[threadIdx.x] = local;
    __syncthreads();
    for (int s = 128; s > 0; s >>= 1) {
        if (threadIdx.x < s) red[threadIdx.x] += red[threadIdx.x + s];
        __syncthreads();
    }
    if (threadIdx.x == 0) g_cst = rsqrtf(red[0] * h);
}

// ---------------- prep: fold scales, merge Wl@Wf, transpose+pad all weights ----------
__global__ void prep_weights_kernel(const float* __restrict__ w0, const float* __restrict__ w1,
                                    const float* __restrict__ w2, const float* __restrict__ w3,
                                    const float* __restrict__ Wl0, const float* __restrict__ Wl1,
                                    const float* __restrict__ Wm1, const float* __restrict__ Wm2,
                                    const float* __restrict__ Wm3,
                                    const float* __restrict__ Wf0, const float* __restrict__ Wf1) {
    int tid = blockIdx.x * blockDim.x + threadIdx.x;
    if (tid >= 28672) return;
    const float INV_S3 = 0.57735026918962576f;
    // PW / (sqrt(U) * sqrt(MUL)) = 0.125 / (8 * sqrt(32))
    const float WSCALE = 0.125f * 0.125f * 0.17677669529663687f;

    if (tid < 12288) {                       // six (64,32) matrices
        int m = tid / 2048, r = tid % 2048;
        int i = r / 32, j = r % 32;          // i = input dim (u), j = output col
        float v; int off;
        if (m == 0)      { v = w0[i * 32 + j];           off = OFF_W0T; }
        else if (m == 1) { v = w1[i * 32 + j] * INV_S3;  off = OFF_W1T; }
        else if (m == 2) { v = w2[i * 32 + j];           off = OFF_W2T; }
        else if (m == 3) { v = w3[i * 32 + j];           off = OFF_W3T; }
        else {
            const float* L = (m == 4) ? Wl0 : Wl1;
            const float* F = (m == 4) ? Wf0 : Wf1;
            float acc = 0.0f;
            for (int w = 0; w < 32; w++) acc = fmaf(L[i * 32 + w], F[w * 32 + j], acc);
            v   = acc * WSCALE;
            off = (m == 4) ? OFF_WAT : OFF_WBT;
        }
        g_wbuf[off + j * PADK + i] = v;
    } else if (tid < 20480) {                // Wm1 / Wm2 (64,64), fold 1/8
        int t2 = tid - 12288;
        int mm = t2 / 4096, r = t2 % 4096;
        int i = r / 64, j = r % 64;
        const float* W = mm ? Wm2 : Wm1;
        g_wbuf[(mm ? OFF_WM2T : OFF_WM1T) + j * PADK + i] = W[i * 64 + j] * 0.125f;
    } else {                                 // Wm3 (64,128), fold 1/8
        int r = tid - 20480;
        int i = r / 128, j = r % 128;
        g_wbuf[OFF_WM3T + j * PADK + i] = Wm3[i * 128 + j] * 0.125f;
    }
}

// ---------------- main: warp-per-row ----------------
__device__ __forceinline__ float dot4(float4 a, float4 b, float acc) {
    acc = fmaf(a.x, b.x, acc); acc = fmaf(a.y, b.y, acc);
    acc = fmaf(a.z, b.z, acc); acc = fmaf(a.w, b.w, acc);
    return acc;
}

__global__ __launch_bounds__(512, 1)
void tp_main_kernel(const float* __restrict__ x1a, const float* __restrict__ x1b,
                    const float4* __restrict__ x2, const float* __restrict__ scalars,
                    float* __restrict__ out, int nrows) {
    extern __shared__ float smem[];
    // cooperative weight load (global prepped buffer -> smem), float4
    {
        const float4* src = (const float4*)g_wbuf;
        float4* dst = (float4*)smem;
        for (int i = threadIdx.x; i < WTOT / 4; i += blockDim.x) dst[i] = src[i];
    }
    __syncthreads();
    const float cst = g_cst;

    const int lid = threadIdx.x & 31;
    const int wid = threadIdx.x >> 5;

    float* S  = smem + WTOT + wid * WARP_STAGE;
    float* s0 = S;            // 64
    float* s1 = S + 64;       // 3*64   [k][u]
    float* t1 = S + 256;      // 64
    float* hb = S + 320;      // 64
    float* wt = S + 384;      // 128
    float* m0 = S + 512;      // 64
    float* m1 = S + 576;      // 3*64
    float* ob = S + 768;      // 128
    float* sc = S + 896;      // 64

    const float* w0t  = smem + OFF_W0T;
    const float* w1t  = smem + OFF_W1T;
    const float* w2t  = smem + OFF_W2T;
    const float* w3t  = smem + OFF_W3T;
    const float* wat  = smem + OFF_WAT;
    const float* wbt  = smem + OFF_WBT;
    const float* wm1t = smem + OFF_WM1T;
    const float* wm2t = smem + OFF_WM2T;
    const float* wm3t = smem + OFF_WM3T;

    const int totw = gridDim.x * NWARP;
    for (int e = blockIdx.x * NWARP + wid; e < nrows; e += totw) {
        // ---- stage row inputs ----
        float4 va = ((const float4*)x1a)[e * 32 + lid];
        float4 vb = ((const float4*)x1b)[e * 32 + lid];
        float4 y  = x2[e];                        // y0=y.x, y1={y.y,y.z,y.w}
        if (lid < 16) {
            ((float4*)sc)[lid] = ((const float4*)scalars)[e * 16 + lid];
        }
        if (lid < 8) {
            *(float4*)&s0[4 * lid]      = va;     // x1a[0:32]
            *(float4*)&s0[32 + 4 * lid] = vb;     // x1b[0:32]
        } else {
            int f = 4 * lid - 32;                 // 0..92
            float av[4] = {va.x, va.y, va.z, va.w};
            float bv[4] = {vb.x, vb.y, vb.z, vb.w};
#pragma unroll
            for (int t = 0; t < 4; t++) {
                int u = (f + t) / 3, k = (f + t) % 3;
                s1[k * 64 + u]      = av[t];      // x1a[32+3u+k]
                s1[k * 64 + 32 + u] = bv[t];      // x1b[32+3u+k]
            }
        }
        __syncwarp();

        // ---- t1[u] = s1[u,:] . y1 ---- and ---- MLP layer 1 ----
        {
            float ta = s1[lid]       * y.y;
            ta = fmaf(s1[64 + lid],  y.z, ta);
            ta = fmaf(s1[128 + lid], y.w, ta);
            float tb = s1[32 + lid]  * y.y;
            tb = fmaf(s1[96 + lid],  y.z, tb);
            tb = fmaf(s1[160 + lid], y.w, tb);
            t1[lid]      = ta;
            t1[lid + 32] = tb;
        }
        float a0 = 0.f, a1 = 0.f;
#pragma unroll
        for (int i = 0; i < 64; i += 4) {
            float4 t  = *(const float4*)&sc[i];
            float4 wa = *(const float4*)&wm1t[lid * PADK + i];
            float4 wb = *(const float4*)&wm1t[(lid + 32) * PADK + i];
            a0 = dot4(t, wa, a0);
            a1 = dot4(t, wb, a1);
        }
        __syncwarp();
        hb[lid]      = cst * a0 / (1.0f + __expf(-a0));
        hb[lid + 32] = cst * a1 / (1.0f + __expf(-a1));
        __syncwarp();

        // ---- MLP layer 2 ----
        a0 = 0.f; a1 = 0.f;
#pragma unroll
        for (int i = 0; i < 64; i += 4) {
            float4 t  = *(const float4*)&hb[i];
            float4 wa = *(const float4*)&wm2t[lid * PADK + i];
            float4 wb = *(const float4*)&wm2t[(lid + 32) * PADK + i];
            a0 = dot4(t, wa, a0);
            a1 = dot4(t, wb, a1);
        }
        __syncwarp();
        hb[lid]      = cst * a0 / (1.0f + __expf(-a0));
        hb[lid + 32] = cst * a1 / (1.0f + __expf(-a1));
        __syncwarp();

        // ---- MLP layer 3: weights[128] ----
        {
            float b0 = 0.f, b1 = 0.f, b2 = 0.f, b3 = 0.f;
#pragma unroll
            for (int i = 0; i < 64; i += 4) {
                float4 t = *(const float4*)&hb[i];
                b0 = dot4(t, *(const float4*)&wm3t[lid * PADK + i],        b0);
                b1 = dot4(t, *(const float4*)&wm3t[(lid + 32) * PADK + i], b1);
                b2 = dot4(t, *(const float4*)&wm3t[(lid + 64) * PADK + i], b2);
                b3 = dot4(t, *(const float4*)&wm3t[(lid + 96) * PADK + i], b3);
            }
            wt[lid]      = b0;
            wt[lid + 32] = b1;
            wt[lid + 64] = b2;
            wt[lid + 96] = b3;
        }
        __syncwarp();

        // ---- TP stage-1 mat-vecs: r0 = s0@w0, p = s0@w2, r1 = t1@w1s, qk = s1k@w3 ----
        float r0 = 0.f, r1 = 0.f, p = 0.f, q0 = 0.f, q1 = 0.f, q2 = 0.f;
#pragma unroll
        for (int i = 0; i < 64; i += 4) {
            float4 ts0 = *(const float4*)&s0[i];
            float4 tt1 = *(const float4*)&t1[i];
            float4 u0  = *(const float4*)&s1[i];
            float4 u1  = *(const float4*)&s1[64 + i];
            float4 u2  = *(const float4*)&s1[128 + i];
            float4 w0v = *(const float4*)&w0t[lid * PADK + i];
            float4 w1v = *(const float4*)&w1t[lid * PADK + i];
            float4 w2v = *(const float4*)&w2t[lid * PADK + i];
            float4 w3v = *(const float4*)&w3t[lid * PADK + i];
            r0 = dot4(ts0, w0v, r0);
            p  = dot4(ts0, w2v, p);
            r1 = dot4(tt1, w1v, r1);
            q0 = dot4(u0,  w3v, q0);
            q1 = dot4(u1,  w3v, q1);
            q2 = dot4(u2,  w3v, q2);
        }

        // ---- build m0, m1 (scales folded: PW->WA/WB, INV_S3->w1) ----
        {
            float wp = wt[64 + lid], wq = wt[96 + lid];
            m0[lid]        = y.x * r0 * wt[lid];
            m0[32 + lid]   = r1 * wt[32 + lid];
            m1[lid]        = y.y * p  * wp;       // k=0, mid2 part
            m1[32 + lid]   = y.x * q0 * wq;       // k=0, mid3 part
            m1[64 + lid]   = y.z * p  * wp;
            m1[96 + lid]   = y.x * q1 * wq;
            m1[128 + lid]  = y.w * p  * wp;
            m1[160 + lid]  = y.x * q2 * wq;
        }
        __syncwarp();

        // ---- final merged linears: o0 = m0@WA, o1k = m1k@WB ----
        float o0 = 0.f, c0 = 0.f, c1 = 0.f, c2 = 0.f;
#pragma unroll
        for (int i = 0; i < 64; i += 4) {
            float4 tm0 = *(const float4*)&m0[i];
            float4 tk0 = *(const float4*)&m1[i];
            float4 tk1 = *(const float4*)&m1[64 + i];
            float4 tk2 = *(const float4*)&m1[128 + i];
            float4 wav = *(const float4*)&wat[lid * PADK + i];
            float4 wbv = *(const float4*)&wbt[lid * PADK + i];
            o0 = dot4(tm0, wav, o0);
            c0 = dot4(tk0, wbv, c0);
            c1 = dot4(tk1, wbv, c1);
            c2 = dot4(tk2, wbv, c2);
        }

        // ---- stage + coalesced store ----
        ob[lid]              = o0;
        ob[32 + 3 * lid + 0] = c0;
        ob[32 + 3 * lid + 1] = c1;
        ob[32 + 3 * lid + 2] = c2;
        __syncwarp();
        ((float4*)out)[e * 32 + lid] = *(const float4*)&ob[4 * lid];
        __syncwarp();
    }
}

// ---------------- launch ----------------
extern "C" void kernel_launch(void* const* d_in, const int* in_sizes, int n_in,
                              void* d_out, int out_size) {
    const float* x1a     = (const float*)d_in[0];
    const float* x1b     = (const float*)d_in[1];
    const float* x2      = (const float*)d_in[2];
    const float* scalars = (const float*)d_in[3];
    const float* w0      = (const float*)d_in[4];
    const float* w1      = (const float*)d_in[5];
    const float* w2      = (const float*)d_in[6];
    const float* w3      = (const float*)d_in[7];
    const float* Wl0     = (const float*)d_in[8];
    const float* Wl1     = (const float*)d_in[9];
    const float* Wm1     = (const float*)d_in[10];
    const float* Wm2     = (const float*)d_in[11];
    const float* Wm3     = (const float*)d_in[12];
    const float* Wf0     = (const float*)d_in[13];
    const float* Wf1     = (const float*)d_in[14];
    int n = in_sizes[0] / 128;

    cudaFuncSetAttribute(tp_main_kernel, cudaFuncAttributeMaxDynamicSharedMemorySize, SMEM_BYTES);

    prep_cst_kernel<<<1, 256>>>();
    prep_weights_kernel<<<112, 256>>>(w0, w1, w2, w3, Wl0, Wl1, Wm1, Wm2, Wm3, Wf0, Wf1);
    tp_main_kernel<<<152, 512, SMEM_BYTES>>>(x1a, x1b, (const float4*)x2, scalars,
                                             (float*)d_out, n);
}

// round 2
// speedup vs baseline: 1.4351x; 1.4351x over previous
#include <cuda_runtime.h>
#include <math.h>

// ---------------- constants ----------------
#define PADK         68        // padded column stride (floats) -> conflict-free LDS.128
#define OFF_W0T      0
#define OFF_W1T      2176
#define OFF_W2T      4352
#define OFF_W3T      6528
#define OFF_WAT      8704
#define OFF_WBT      10880
#define OFF_WM1T     13056
#define OFF_WM2T     17408
#define OFF_WM3T     21760
#define WTOT         30464     // total weight floats in smem
#define NWARP        12
#define RPW          4         // rows per warp
#define RS           512       // staging floats per row (with overlays)
#define SMEM_FLOATS  (WTOT + NWARP * RPW * RS)     // 30464 + 24576 = 55040
#define SMEM_BYTES   (SMEM_FLOATS * 4)             // 220160

__device__ float g_cst;
__device__ float g_wbuf[WTOT];

// ---------------- prep: silu normalization constant (trapz, matches numpy) -------------
__global__ void prep_cst_kernel() {
    const int   N = 20000;
    const float h = 24.0f / 20000.0f;
    float local = 0.0f;
    for (int i = threadIdx.x; i <= N; i += blockDim.x) {
        float z   = -12.0f + h * (float)i;
        float s   = z / (1.0f + __expf(-z));
        float phi = __expf(-0.5f * z * z) * 0.3989422804014327f;
        float f   = s * s * phi;
        if (i == 0 || i == N) f *= 0.5f;
        local += f;
    }
    __shared__ float red[256];
    red[threadIdx.x] = local;
    __syncthreads();
    for (int s = 128; s > 0; s >>= 1) {
        if (threadIdx.x < s) red[threadIdx.x] += red[threadIdx.x + s];
        __syncthreads();
    }
    if (threadIdx.x == 0) g_cst = rsqrtf(red[0] * h);
}

// ---------------- prep: fold scales, merge Wl@Wf, transpose+pad all weights ----------
__global__ void prep_weights_kernel(const float* __restrict__ w0, const float* __restrict__ w1,
                                    const float* __restrict__ w2, const float* __restrict__ w3,
                                    const float* __restrict__ Wl0, const float* __restrict__ Wl1,
                                    const float* __restrict__ Wm1, const float* __restrict__ Wm2,
                                    const float* __restrict__ Wm3,
                                    const float* __restrict__ Wf0, const float* __restrict__ Wf1) {
    int tid = blockIdx.x * blockDim.x + threadIdx.x;
    if (tid >= 28672) return;
    const float INV_S3 = 0.57735026918962576f;
    const float WSCALE = 0.125f * 0.125f * 0.17677669529663687f;  // PW/(sqrt(U)*sqrt(MUL))

    if (tid < 12288) {                       // six (64,32) matrices
        int m = tid / 2048, r = tid % 2048;
        int i = r / 32, j = r % 32;
        float v; int off;
        if (m == 0)      { v = w0[i * 32 + j];           off = OFF_W0T; }
        else if (m == 1) { v = w1[i * 32 + j] * INV_S3;  off = OFF_W1T; }
        else if (m == 2) { v = w2[i * 32 + j];           off = OFF_W2T; }
        else if (m == 3) { v = w3[i * 32 + j];           off = OFF_W3T; }
        else {
            const float* L = (m == 4) ? Wl0 : Wl1;
            const float* F = (m == 4) ? Wf0 : Wf1;
            float acc = 0.0f;
            for (int w = 0; w < 32; w++) acc = fmaf(L[i * 32 + w], F[w * 32 + j], acc);
            v   = acc * WSCALE;
            off = (m == 4) ? OFF_WAT : OFF_WBT;
        }
        g_wbuf[off + j * PADK + i] = v;
    } else if (tid < 20480) {                // Wm1 / Wm2 (64,64), fold 1/8
        int t2 = tid - 12288;
        int mm = t2 / 4096, r = t2 % 4096;
        int i = r / 64, j = r % 64;
        const float* W = mm ? Wm2 : Wm1;
        g_wbuf[(mm ? OFF_WM2T : OFF_WM1T) + j * PADK + i] = W[i * 64 + j] * 0.125f;
    } else {                                 // Wm3 (64,128), fold 1/8
        int r = tid - 20480;
        int i = r / 128, j = r % 128;
        g_wbuf[OFF_WM3T + j * PADK + i] = Wm3[i * 128 + j] * 0.125f;
    }
}

// ---------------- main: warp handles 4 rows; weights amortized across them ----------------
__device__ __forceinline__ float dot4(float4 a, float4 b, float acc) {
    acc = fmaf(a.x, b.x, acc); acc = fmaf(a.y, b.y, acc);
    acc = fmaf(a.z, b.z, acc); acc = fmaf(a.w, b.w, acc);
    return acc;
}

// staging layout per row (RS=512 floats):
//   [0:64)    s0        -> overlay m0 after TP stage 1
//   [64:256)  s1 [k][u] -> overlay m1 after TP stage 1
//   [256:320) t1        -> overlay ob (with [320:384)) after final loop
//   [320:384) sc, then hb
//   [384:512) wt (128)

__global__ __launch_bounds__(384, 1)
void tp_main_kernel(const float* __restrict__ x1a, const float* __restrict__ x1b,
                    const float4* __restrict__ x2, const float* __restrict__ scalars,
                    float* __restrict__ out, int nrows) {
    extern __shared__ float smem[];
    {
        const float4* src = (const float4*)g_wbuf;
        float4* dst = (float4*)smem;
        for (int i = threadIdx.x; i < WTOT / 4; i += blockDim.x) dst[i] = src[i];
    }
    __syncthreads();
    const float cst = g_cst;

    const int lid = threadIdx.x & 31;
    const int wid = threadIdx.x >> 5;

    float* Sw = smem + WTOT + wid * (RPW * RS);
#define SS0(r) (Sw + (r) * RS)
#define SS1(r) (Sw + (r) * RS + 64)
#define ST1(r) (Sw + (r) * RS + 256)
#define SHB(r) (Sw + (r) * RS + 320)
#define SWT(r) (Sw + (r) * RS + 384)
#define SM0(r) (Sw + (r) * RS)
#define SM1(r) (Sw + (r) * RS + 64)
#define SOB(r) (Sw + (r) * RS + 256)

    const float* w0t  = smem + OFF_W0T;
    const float* w1t  = smem + OFF_W1T;
    const float* w2t  = smem + OFF_W2T;
    const float* w3t  = smem + OFF_W3T;
    const float* wat  = smem + OFF_WAT;
    const float* wbt  = smem + OFF_WBT;
    const float* wm1t = smem + OFF_WM1T;
    const float* wm2t = smem + OFF_WM2T;
    const float* wm3t = smem + OFF_WM3T;

    const int gstride = gridDim.x * NWARP * RPW;
    for (int e = (blockIdx.x * NWARP + wid) * RPW; e < nrows; e += gstride) {
        // ---- stage 4 rows ----
        float4 yv[RPW];
#pragma unroll
        for (int r = 0; r < RPW; r++) {
            int row = e + r;
            if (row >= nrows) break;
            float4 va = ((const float4*)x1a)[row * 32 + lid];
            float4 vb = ((const float4*)x1b)[row * 32 + lid];
            yv[r] = x2[row];
            if (lid < 16) ((float4*)SHB(r))[lid] = ((const float4*)scalars)[row * 16 + lid];
            float* s0 = SS0(r); float* s1 = SS1(r);
            if (lid < 8) {
                *(float4*)&s0[4 * lid]      = va;
                *(float4*)&s0[32 + 4 * lid] = vb;
            } else {
                int f = 4 * lid - 32;
                float av[4] = {va.x, va.y, va.z, va.w};
                float bv[4] = {vb.x, vb.y, vb.z, vb.w};
#pragma unroll
                for (int t = 0; t < 4; t++) {
                    int u = (f + t) / 3, k = (f + t) % 3;
                    s1[k * 64 + u]      = av[t];
                    s1[k * 64 + 32 + u] = bv[t];
                }
            }
        }
        __syncwarp();

        // ---- t1[u] = s1[u,:] . y1 for each row ----
#pragma unroll
        for (int r = 0; r < RPW; r++) {
            float* s1 = SS1(r); float* t1 = ST1(r);
            float ta = s1[lid]       * yv[r].y;
            ta = fmaf(s1[64 + lid],  yv[r].z, ta);
            ta = fmaf(s1[128 + lid], yv[r].w, ta);
            float tb = s1[32 + lid]  * yv[r].y;
            tb = fmaf(s1[96 + lid],  yv[r].z, tb);
            tb = fmaf(s1[160 + lid], yv[r].w, tb);
            t1[lid]      = ta;
            t1[lid + 32] = tb;
        }

        // ---- MLP layer 1 (reads sc in SHB) ----
        {
            float a[2 * RPW] = {0.f};
#pragma unroll
            for (int i = 0; i < 64; i += 4) {
                float4 wa = *(const float4*)&wm1t[lid * PADK + i];
                float4 wb = *(const float4*)&wm1t[(lid + 32) * PADK + i];
#pragma unroll
                for (int r = 0; r < RPW; r++) {
                    float4 t = *(const float4*)&SHB(r)[i];
                    a[2 * r]     = dot4(t, wa, a[2 * r]);
                    a[2 * r + 1] = dot4(t, wb, a[2 * r + 1]);
                }
            }
            __syncwarp();
#pragma unroll
            for (int r = 0; r < RPW; r++) {
                float a0 = a[2 * r], a1 = a[2 * r + 1];
                SHB(r)[lid]      = cst * a0 / (1.0f + __expf(-a0));
                SHB(r)[lid + 32] = cst * a1 / (1.0f + __expf(-a1));
            }
            __syncwarp();
        }

        // ---- MLP layer 2 ----
        {
            float a[2 * RPW] = {0.f};
#pragma unroll
            for (int i = 0; i < 64; i += 4) {
                float4 wa = *(const float4*)&wm2t[lid * PADK + i];
                float4 wb = *(const float4*)&wm2t[(lid + 32) * PADK + i];
#pragma unroll
                for (int r = 0; r < RPW; r++) {
                    float4 t = *(const float4*)&SHB(r)[i];
                    a[2 * r]     = dot4(t, wa, a[2 * r]);
                    a[2 * r + 1] = dot4(t, wb, a[2 * r + 1]);
                }
            }
            __syncwarp();
#pragma unroll
            for (int r = 0; r < RPW; r++) {
                float a0 = a[2 * r], a1 = a[2 * r + 1];
                SHB(r)[lid]      = cst * a0 / (1.0f + __expf(-a0));
                SHB(r)[lid + 32] = cst * a1 / (1.0f + __expf(-a1));
            }
            __syncwarp();
        }

        // ---- MLP layer 3: per-row weights[128] -> wt ----
        {
            float b[4 * RPW] = {0.f};
#pragma unroll
            for (int i = 0; i < 64; i += 4) {
                float4 wv0 = *(const float4*)&wm3t[lid * PADK + i];
                float4 wv1 = *(const float4*)&wm3t[(lid + 32) * PADK + i];
                float4 wv2 = *(const float4*)&wm3t[(lid + 64) * PADK + i];
                float4 wv3 = *(const float4*)&wm3t[(lid + 96) * PADK + i];
#pragma unroll
                for (int r = 0; r < RPW; r++) {
                    float4 t = *(const float4*)&SHB(r)[i];
                    b[4 * r]     = dot4(t, wv0, b[4 * r]);
                    b[4 * r + 1] = dot4(t, wv1, b[4 * r + 1]);
                    b[4 * r + 2] = dot4(t, wv2, b[4 * r + 2]);
                    b[4 * r + 3] = dot4(t, wv3, b[4 * r + 3]);
                }
            }
#pragma unroll
            for (int r = 0; r < RPW; r++) {
                float* wt = SWT(r);
                wt[lid]      = b[4 * r];
                wt[lid + 32] = b[4 * r + 1];
                wt[lid + 64] = b[4 * r + 2];
                wt[lid + 96] = b[4 * r + 3];
            }
            __syncwarp();
        }

        // ---- TP stage 1, loop A: r0 = s0@w0, p = s0@w2, r1 = t1@w1 ----
        float r0a[RPW] = {0.f}, pa[RPW] = {0.f}, r1a[RPW] = {0.f};
#pragma unroll
        for (int i = 0; i < 64; i += 4) {
            float4 w0v = *(const float4*)&w0t[lid * PADK + i];
            float4 w1v = *(const float4*)&w1t[lid * PADK + i];
            float4 w2v = *(const float4*)&w2t[lid * PADK + i];
#pragma unroll
            for (int r = 0; r < RPW; r++) {
                float4 ts0 = *(const float4*)&SS0(r)[i];
                float4 tt1 = *(const float4*)&ST1(r)[i];
                r0a[r] = dot4(ts0, w0v, r0a[r]);
                pa[r]  = dot4(ts0, w2v, pa[r]);
                r1a[r] = dot4(tt1, w1v, r1a[r]);
            }
        }
        // ---- TP stage 1, loop B: qk = s1k@w3 ----
        float qa[3 * RPW] = {0.f};
#pragma unroll
        for (int i = 0; i < 64; i += 4) {
            float4 w3v = *(const float4*)&w3t[lid * PADK + i];
#pragma unroll
            for (int r = 0; r < RPW; r++) {
                float4 u0 = *(const float4*)&SS1(r)[i];
                float4 u1 = *(const float4*)&SS1(r)[64 + i];
                float4 u2 = *(const float4*)&SS1(r)[128 + i];
                qa[3 * r]     = dot4(u0, w3v, qa[3 * r]);
                qa[3 * r + 1] = dot4(u1, w3v, qa[3 * r + 1]);
                qa[3 * r + 2] = dot4(u2, w3v, qa[3 * r + 2]);
            }
        }
        __syncwarp();   // all lanes done reading s0/s1/t1; safe to overlay m0/m1

        // ---- build m0, m1 (scales pre-folded into weight copies) ----
#pragma unroll
        for (int r = 0; r < RPW; r++) {
            float* wt = SWT(r);
            float wp = wt[64 + lid], wq = wt[96 + lid];
            float* m0 = SM0(r); float* m1 = SM1(r);
            m0[lid]       = yv[r].x * r0a[r] * wt[lid];
            m0[32 + lid]  = r1a[r] * wt[32 + lid];
            m1[lid]       = yv[r].y * pa[r] * wp;
            m1[32 + lid]  = yv[r].x * qa[3 * r]     * wq;
            m1[64 + lid]  = yv[r].z * pa[r] * wp;
            m1[96 + lid]  = yv[r].x * qa[3 * r + 1] * wq;
            m1[128 + lid] = yv[r].w * pa[r] * wp;
            m1[160 + lid] = yv[r].x * qa[3 * r + 2] * wq;
        }
        __syncwarp();

        // ---- final merged linears: o0 = m0@WA, o1k = m1k@WB ----
        float o[4 * RPW] = {0.f};
#pragma unroll
        for (int i = 0; i < 64; i += 4) {
            float4 wav = *(const float4*)&wat[lid * PADK + i];
            float4 wbv = *(const float4*)&wbt[lid * PADK + i];
#pragma unroll
            for (int r = 0; r < RPW; r++) {
                float4 tm0 = *(const float4*)&SM0(r)[i];
                float4 tk0 = *(const float4*)&SM1(r)[i];
                float4 tk1 = *(const float4*)&SM1(r)[64 + i];
                float4 tk2 = *(const float4*)&SM1(r)[128 + i];
                o[4 * r]     = dot4(tm0, wav, o[4 * r]);
                o[4 * r + 1] = dot4(tk0, wbv, o[4 * r + 1]);
                o[4 * r + 2] = dot4(tk1, wbv, o[4 * r + 2]);
                o[4 * r + 3] = dot4(tk2, wbv, o[4 * r + 3]);
            }
        }
        __syncwarp();   // done reading m0/m1; safe to overlay ob

        // ---- stage + coalesced store ----
#pragma unroll
        for (int r = 0; r < RPW; r++) {
            float* ob = SOB(r);
            ob[lid]              = o[4 * r];
            ob[32 + 3 * lid + 0] = o[4 * r + 1];
            ob[32 + 3 * lid + 1] = o[4 * r + 2];
            ob[32 + 3 * lid + 2] = o[4 * r + 3];
        }
        __syncwarp();
#pragma unroll
        for (int r = 0; r < RPW; r++) {
            int row = e + r;
            if (row < nrows)
                ((float4*)out)[row * 32 + lid] = *(const float4*)&SOB(r)[4 * lid];
        }
        __syncwarp();
    }
}

// ---------------- launch ----------------
extern "C" void kernel_launch(void* const* d_in, const int* in_sizes, int n_in,
                              void* d_out, int out_size) {
    const float* x1a     = (const float*)d_in[0];
    const float* x1b     = (const float*)d_in[1];
    const float* x2      = (const float*)d_in[2];
    const float* scalars = (const float*)d_in[3];
    const float* w0      = (const float*)d_in[4];
    const float* w1      = (const float*)d_in[5];
    const float* w2      = (const float*)d_in[6];
    const float* w3      = (const float*)d_in[7];
    const float* Wl0     = (const float*)d_in[8];
    const float* Wl1     = (const float*)d_in[9];
    const float* Wm1     = (const float*)d_in[10];
    const float* Wm2     = (const float*)d_in[11];
    const float* Wm3     = (const float*)d_in[12];
    const float* Wf0     = (const float*)d_in[13];
    const float* Wf1     = (const float*)d_in[14];
    int n = in_sizes[0] / 128;

    cudaFuncSetAttribute(tp_main_kernel, cudaFuncAttributeMaxDynamicSharedMemorySize, SMEM_BYTES);

    prep_cst_kernel<<<1, 256>>>();
    prep_weights_kernel<<<112, 256>>>(w0, w1, w2, w3, Wl0, Wl1, Wm1, Wm2, Wm3, Wf0, Wf1);
    tp_main_kernel<<<148, 384, SMEM_BYTES>>>(x1a, x1b, (const float4*)x2, scalars,
                                             (float*)d_out, n);
}

// round 3
// speedup vs baseline: 1.6616x; 1.1578x over previous
#include <cuda_runtime.h>
#include <math.h>

// ---------------- constants ----------------
#define PADK         68        // padded column stride (floats) -> conflict-free LDS.128
#define OFF_W0T      0
#define OFF_W1T      2176
#define OFF_W2T      4352
#define OFF_W3T      6528
#define OFF_WAT      8704
#define OFF_WBT      10880
#define OFF_WM1T     13056
#define OFF_WM2T     17408
#define OFF_WM3T     21760
#define WTOT         30464     // total weight floats in smem
#define NWARP        12
#define RS2          768       // floats per row-PAIR (interleaved)
// pair-local float offsets (each logical element is 2 floats: {rowA,rowB})
#define PS0          0         // s0: 64 elems  -> overlay m0
#define PS1          128       // s1: 192 elems ([k][u], k stride 128 floats) -> overlay m1
#define PT1          512       // t1: 64 elems  -> overlay ob (rowA at PT1, rowB at PT1+128)
#define PHB          640       // sc then hb: 64 elems
#define SMEM_FLOATS  (WTOT + NWARP * 2 * RS2)   // 30464 + 18432 = 48896
#define SMEM_BYTES   (SMEM_FLOATS * 4)          // 195584

__device__ float g_cst;
__device__ float g_wbuf[WTOT];

// ---------------- packed f32x2 helpers ----------------
typedef unsigned long long u64;
__device__ __forceinline__ u64 pk2(float lo, float hi) {
    u64 d; asm("mov.b64 %0,{%1,%2};" : "=l"(d) : "f"(lo), "f"(hi)); return d;
}
__device__ __forceinline__ u64 dup2(float w) {
    u64 d; asm("mov.b64 %0,{%1,%1};" : "=l"(d) : "f"(w)); return d;
}
__device__ __forceinline__ u64 f2fma(u64 a, u64 b, u64 c) {
    u64 d; asm("fma.rn.f32x2 %0,%1,%2,%3;" : "=l"(d) : "l"(a), "l"(b), "l"(c)); return d;
}
__device__ __forceinline__ u64 f2mul(u64 a, u64 b) {
    u64 d; asm("mul.rn.f32x2 %0,%1,%2;" : "=l"(d) : "l"(a), "l"(b)); return d;
}
__device__ __forceinline__ void upk2(u64 v, float& lo, float& hi) {
    asm("mov.b64 {%0,%1},%2;" : "=f"(lo), "=f"(hi) : "l"(v));
}

#define DUP4(nm, v4) u64 nm##x = dup2((v4).x), nm##y = dup2((v4).y), \
                         nm##z = dup2((v4).z), nm##w = dup2((v4).w)
#define FMA4(acc, t0, t1, W) do { \
    acc = f2fma((t0).x, W##x, acc); acc = f2fma((t0).y, W##y, acc); \
    acc = f2fma((t1).x, W##z, acc); acc = f2fma((t1).y, W##w, acc); } while (0)

// ---------------- prep: cst (block 0) + fold scales, merge Wl@Wf, transpose+pad ----------
__global__ void prep_kernel(const float* __restrict__ w0, const float* __restrict__ w1,
                            const float* __restrict__ w2, const float* __restrict__ w3,
                            const float* __restrict__ Wl0, const float* __restrict__ Wl1,
                            const float* __restrict__ Wm1, const float* __restrict__ Wm2,
                            const float* __restrict__ Wm3,
                            const float* __restrict__ Wf0, const float* __restrict__ Wf1) {
    // --- block 0: silu normalization constant by trapezoid quadrature ---
    if (blockIdx.x == 0) {
        const int   N = 20000;
        const float h = 24.0f / 20000.0f;
        float local = 0.0f;
        for (int i = threadIdx.x; i <= N; i += blockDim.x) {
            float z   = -12.0f + h * (float)i;
            float s   = z / (1.0f + __expf(-z));
            float phi = __expf(-0.5f * z * z) * 0.3989422804014327f;
            float f   = s * s * phi;
            if (i == 0 || i == N) f *= 0.5f;
            local += f;
        }
        __shared__ float red[256];
        red[threadIdx.x] = local;
        __syncthreads();
        for (int s = 128; s > 0; s >>= 1) {
            if (threadIdx.x < s) red[threadIdx.x] += red[threadIdx.x + s];
            __syncthreads();
        }
        if (threadIdx.x == 0) g_cst = rsqrtf(red[0] * h);
    }

    int tid = blockIdx.x * blockDim.x + threadIdx.x;
    if (tid >= 28672) return;
    const float INV_S3 = 0.57735026918962576f;
    const float WSCALE = 0.125f * 0.125f * 0.17677669529663687f;  // PW/(sqrt(U)*sqrt(MUL))

    if (tid < 12288) {                       // six (64,32) matrices
        int m = tid / 2048, r = tid % 2048;
        int i = r / 32, j = r % 32;
        float v; int off;
        if (m == 0)      { v = w0[i * 32 + j];           off = OFF_W0T; }
        else if (m == 1) { v = w1[i * 32 + j] * INV_S3;  off = OFF_W1T; }
        else if (m == 2) { v = w2[i * 32 + j];           off = OFF_W2T; }
        else if (m == 3) { v = w3[i * 32 + j];           off = OFF_W3T; }
        else {
            const float* L = (m == 4) ? Wl0 : Wl1;
            const float* F = (m == 4) ? Wf0 : Wf1;
            float acc = 0.0f;
            for (int w = 0; w < 32; w++) acc = fmaf(L[i * 32 + w], F[w * 32 + j], acc);
            v   = acc * WSCALE;
            off = (m == 4) ? OFF_WAT : OFF_WBT;
        }
        g_wbuf[off + j * PADK + i] = v;
    } else if (tid < 20480) {                // Wm1 / Wm2 (64,64), fold 1/8
        int t2 = tid - 12288;
        int mm = t2 / 4096, r = t2 % 4096;
        int i = r / 64, j = r % 64;
        const float* W = mm ? Wm2 : Wm1;
        g_wbuf[(mm ? OFF_WM2T : OFF_WM1T) + j * PADK + i] = W[i * 64 + j] * 0.125f;
    } else {                                 // Wm3 (64,128), fold 1/8
        int r = tid - 20480;
        int i = r / 128, j = r % 128;
        g_wbuf[OFF_WM3T + j * PADK + i] = Wm3[i * 128 + j] * 0.125f;
    }
}

// ---------------- main: warp = 2 row-pairs, f32x2 packed math ----------------
__global__ __launch_bounds__(384, 1)
void tp_main_kernel(const float* __restrict__ x1a, const float* __restrict__ x1b,
                    const float4* __restrict__ x2, const float* __restrict__ scalars,
                    float* __restrict__ out, int nrows) {
    extern __shared__ float smem[];
    {
        const float4* src = (const float4*)g_wbuf;
        float4* dst = (float4*)smem;
        for (int i = threadIdx.x; i < WTOT / 4; i += blockDim.x) dst[i] = src[i];
    }
    __syncthreads();
    const float cst = g_cst;

    const int lid = threadIdx.x & 31;
    const int wid = threadIdx.x >> 5;

    float* Sw = smem + WTOT + wid * (2 * RS2);

    const float* w0t  = smem + OFF_W0T;
    const float* w1t  = smem + OFF_W1T;
    const float* w2t  = smem + OFF_W2T;
    const float* w3t  = smem + OFF_W3T;
    const float* wat  = smem + OFF_WAT;
    const float* wbt  = smem + OFF_WBT;
    const float* wm1t = smem + OFF_WM1T;
    const float* wm2t = smem + OFF_WM2T;
    const float* wm3t = smem + OFF_WM3T;

    const int gstride = gridDim.x * NWARP * 4;
    for (int e = (blockIdx.x * NWARP + wid) * 4; e < nrows; e += gstride) {
        // ---- stage 4 rows (2 interleaved pairs); nrows % 4 == 0 ----
        float4 yv4[4];
#pragma unroll
        for (int r = 0; r < 4; r++) {
            int row = e + r;
            float* P = Sw + (r >> 1) * RS2;
            int h = r & 1;
            float4 va = ((const float4*)x1a)[row * 32 + lid];
            float4 vb = ((const float4*)x1b)[row * 32 + lid];
            yv4[r] = x2[row];
            if (lid < 16) {
                float4 s = ((const float4*)scalars)[row * 16 + lid];
                int b0 = PHB + 8 * lid + h;
                P[b0] = s.x; P[b0 + 2] = s.y; P[b0 + 4] = s.z; P[b0 + 6] = s.w;
            }
            if (lid < 8) {
                int b0 = PS0 + 8 * lid + h;
                P[b0] = va.x; P[b0 + 2] = va.y; P[b0 + 4] = va.z; P[b0 + 6] = va.w;
                int b1 = PS0 + 64 + 8 * lid + h;
                P[b1] = vb.x; P[b1 + 2] = vb.y; P[b1 + 4] = vb.z; P[b1 + 6] = vb.w;
            } else {
                int f = 4 * lid - 32;
                float av[4] = {va.x, va.y, va.z, va.w};
                float bv[4] = {vb.x, vb.y, vb.z, vb.w};
#pragma unroll
                for (int t = 0; t < 4; t++) {
                    int u = (f + t) / 3, k = (f + t) % 3;
                    P[PS1 + k * 128 + 2 * u + h]      = av[t];
                    P[PS1 + k * 128 + 64 + 2 * u + h] = bv[t];
                }
            }
        }
        __syncwarp();

        // packed y components per pair
        u64 Y0[2], Y1[2], Y2[2], Y3[2];
#pragma unroll
        for (int p = 0; p < 2; p++) {
            Y0[p] = pk2(yv4[2 * p].x, yv4[2 * p + 1].x);
            Y1[p] = pk2(yv4[2 * p].y, yv4[2 * p + 1].y);
            Y2[p] = pk2(yv4[2 * p].z, yv4[2 * p + 1].z);
            Y3[p] = pk2(yv4[2 * p].w, yv4[2 * p + 1].w);
        }

        // ---- t1[u] = s1[u,:] . y1 (packed) ----
#pragma unroll
        for (int p = 0; p < 2; p++) {
            float* P = Sw + p * RS2;
            u64 a = f2mul(*(const u64*)&P[PS1 + 2 * lid], Y1[p]);
            a = f2fma(*(const u64*)&P[PS1 + 128 + 2 * lid], Y2[p], a);
            a = f2fma(*(const u64*)&P[PS1 + 256 + 2 * lid], Y3[p], a);
            *(u64*)&P[PT1 + 2 * lid] = a;
            u64 b = f2mul(*(const u64*)&P[PS1 + 64 + 2 * lid], Y1[p]);
            b = f2fma(*(const u64*)&P[PS1 + 192 + 2 * lid], Y2[p], b);
            b = f2fma(*(const u64*)&P[PS1 + 320 + 2 * lid], Y3[p], b);
            *(u64*)&P[PT1 + 64 + 2 * lid] = b;
        }

        // ---- MLP layer 1 ----
        {
            u64 a0[2] = {0, 0}, a1[2] = {0, 0};
#pragma unroll
            for (int i = 0; i < 64; i += 4) {
                float4 wa = *(const float4*)&wm1t[lid * PADK + i];
                float4 wb = *(const float4*)&wm1t[(lid + 32) * PADK + i];
                DUP4(WA, wa); DUP4(WB, wb);
#pragma unroll
                for (int p = 0; p < 2; p++) {
                    const float* P = Sw + p * RS2;
                    ulonglong2 t0 = *(const ulonglong2*)&P[PHB + 2 * i];
                    ulonglong2 t1 = *(const ulonglong2*)&P[PHB + 2 * i + 4];
                    FMA4(a0[p], t0, t1, WA);
                    FMA4(a1[p], t0, t1, WB);
                }
            }
            __syncwarp();
#pragma unroll
            for (int p = 0; p < 2; p++) {
                float* P = Sw + p * RS2;
                float l0, h0, l1, h1;
                upk2(a0[p], l0, h0); upk2(a1[p], l1, h1);
                l0 = cst * l0 / (1.0f + __expf(-l0)); h0 = cst * h0 / (1.0f + __expf(-h0));
                l1 = cst * l1 / (1.0f + __expf(-l1)); h1 = cst * h1 / (1.0f + __expf(-h1));
                *(u64*)&P[PHB + 2 * lid]      = pk2(l0, h0);
                *(u64*)&P[PHB + 64 + 2 * lid] = pk2(l1, h1);
            }
            __syncwarp();
        }

        // ---- MLP layer 2 ----
        {
            u64 a0[2] = {0, 0}, a1[2] = {0, 0};
#pragma unroll
            for (int i = 0; i < 64; i += 4) {
                float4 wa = *(const float4*)&wm2t[lid * PADK + i];
                float4 wb = *(const float4*)&wm2t[(lid + 32) * PADK + i];
                DUP4(WA, wa); DUP4(WB, wb);
#pragma unroll
                for (int p = 0; p < 2; p++) {
                    const float* P = Sw + p * RS2;
                    ulonglong2 t0 = *(const ulonglong2*)&P[PHB + 2 * i];
                    ulonglong2 t1 = *(const ulonglong2*)&P[PHB + 2 * i + 4];
                    FMA4(a0[p], t0, t1, WA);
                    FMA4(a1[p], t0, t1, WB);
                }
            }
            __syncwarp();
#pragma unroll
            for (int p = 0; p < 2; p++) {
                float* P = Sw + p * RS2;
                float l0, h0, l1, h1;
                upk2(a0[p], l0, h0); upk2(a1[p], l1, h1);
                l0 = cst * l0 / (1.0f + __expf(-l0)); h0 = cst * h0 / (1.0f + __expf(-h0));
                l1 = cst * l1 / (1.0f + __expf(-l1)); h1 = cst * h1 / (1.0f + __expf(-h1));
                *(u64*)&P[PHB + 2 * lid]      = pk2(l0, h0);
                *(u64*)&P[PHB + 64 + 2 * lid] = pk2(l1, h1);
            }
            __syncwarp();
        }

        // ---- MLP layer 3: weights[128] kept in registers (same-lane use only) ----
        u64 b0[2] = {0, 0}, b1[2] = {0, 0}, b2[2] = {0, 0}, b3[2] = {0, 0};
#pragma unroll
        for (int i = 0; i < 64; i += 4) {
            float4 wv0 = *(const float4*)&wm3t[lid * PADK + i];
            float4 wv1 = *(const float4*)&wm3t[(lid + 32) * PADK + i];
            float4 wv2 = *(const float4*)&wm3t[(lid + 64) * PADK + i];
            float4 wv3 = *(const float4*)&wm3t[(lid + 96) * PADK + i];
            DUP4(W0, wv0); DUP4(W1, wv1); DUP4(W2, wv2); DUP4(W3, wv3);
#pragma unroll
            for (int p = 0; p < 2; p++) {
                const float* P = Sw + p * RS2;
                ulonglong2 t0 = *(const ulonglong2*)&P[PHB + 2 * i];
                ulonglong2 t1 = *(const ulonglong2*)&P[PHB + 2 * i + 4];
                FMA4(b0[p], t0, t1, W0);
                FMA4(b1[p], t0, t1, W1);
                FMA4(b2[p], t0, t1, W2);
                FMA4(b3[p], t0, t1, W3);
            }
        }

        // ---- TP stage 1, loop A: r0 = s0@w0, p = s0@w2, r1 = t1@w1 ----
        u64 R0[2] = {0, 0}, PPa[2] = {0, 0}, R1[2] = {0, 0};
#pragma unroll
        for (int i = 0; i < 64; i += 4) {
            float4 w0v = *(const float4*)&w0t[lid * PADK + i];
            float4 w1v = *(const float4*)&w1t[lid * PADK + i];
            float4 w2v = *(const float4*)&w2t[lid * PADK + i];
            DUP4(W0, w0v); DUP4(W1, w1v); DUP4(W2, w2v);
#pragma unroll
            for (int p = 0; p < 2; p++) {
                const float* P = Sw + p * RS2;
                ulonglong2 s0a = *(const ulonglong2*)&P[PS0 + 2 * i];
                ulonglong2 s0b = *(const ulonglong2*)&P[PS0 + 2 * i + 4];
                ulonglong2 t1a = *(const ulonglong2*)&P[PT1 + 2 * i];
                ulonglong2 t1b = *(const ulonglong2*)&P[PT1 + 2 * i + 4];
                FMA4(R0[p],  s0a, s0b, W0);
                FMA4(PPa[p], s0a, s0b, W2);
                FMA4(R1[p],  t1a, t1b, W1);
            }
        }
        // ---- TP stage 1, loop B: qk = s1k@w3 ----
        u64 Q0[2] = {0, 0}, Q1[2] = {0, 0}, Q2[2] = {0, 0};
#pragma unroll
        for (int i = 0; i < 64; i += 4) {
            float4 w3v = *(const float4*)&w3t[lid * PADK + i];
            DUP4(W3, w3v);
#pragma unroll
            for (int p = 0; p < 2; p++) {
                const float* P = Sw + p * RS2;
                ulonglong2 u0a = *(const ulonglong2*)&P[PS1 + 2 * i];
                ulonglong2 u0b = *(const ulonglong2*)&P[PS1 + 2 * i + 4];
                ulonglong2 u1a = *(const ulonglong2*)&P[PS1 + 128 + 2 * i];
                ulonglong2 u1b = *(const ulonglong2*)&P[PS1 + 128 + 2 * i + 4];
                ulonglong2 u2a = *(const ulonglong2*)&P[PS1 + 256 + 2 * i];
                ulonglong2 u2b = *(const ulonglong2*)&P[PS1 + 256 + 2 * i + 4];
                FMA4(Q0[p], u0a, u0b, W3);
                FMA4(Q1[p], u1a, u1b, W3);
                FMA4(Q2[p], u2a, u2b, W3);
            }
        }
        __syncwarp();   // done reading s0/s1/t1 -> safe to overlay m0/m1

        // ---- build m0, m1 (packed; scales pre-folded) ----
#pragma unroll
        for (int p = 0; p < 2; p++) {
            float* P = Sw + p * RS2;
            u64 pw   = f2mul(PPa[p], b2[p]);       // p * wt[64+lid]
            u64 y0wq = f2mul(Y0[p], b3[p]);        // y0 * wt[96+lid]
            *(u64*)&P[PS0 + 2 * lid]       = f2mul(f2mul(Y0[p], R0[p]), b0[p]);
            *(u64*)&P[PS0 + 64 + 2 * lid]  = f2mul(R1[p], b1[p]);
            *(u64*)&P[PS1 + 2 * lid]       = f2mul(Y1[p], pw);
            *(u64*)&P[PS1 + 64 + 2 * lid]  = f2mul(Q0[p], y0wq);
            *(u64*)&P[PS1 + 128 + 2 * lid] = f2mul(Y2[p], pw);
            *(u64*)&P[PS1 + 192 + 2 * lid] = f2mul(Q1[p], y0wq);
            *(u64*)&P[PS1 + 256 + 2 * lid] = f2mul(Y3[p], pw);
            *(u64*)&P[PS1 + 320 + 2 * lid] = f2mul(Q2[p], y0wq);
        }
        __syncwarp();

        // ---- final merged linears: o0 = m0@WA, o1k = m1k@WB ----
        u64 O0[2] = {0, 0}, O1[2] = {0, 0}, O2[2] = {0, 0}, O3[2] = {0, 0};
#pragma unroll
        for (int i = 0; i < 64; i += 4) {
            float4 wav = *(const float4*)&wat[lid * PADK + i];
            float4 wbv = *(const float4*)&wbt[lid * PADK + i];
            DUP4(WA, wav); DUP4(WB, wbv);
#pragma unroll
            for (int p = 0; p < 2; p++) {
                const float* P = Sw + p * RS2;
                ulonglong2 m0a = *(const ulonglong2*)&P[PS0 + 2 * i];
                ulonglong2 m0b = *(const ulonglong2*)&P[PS0 + 2 * i + 4];
                ulonglong2 k0a = *(const ulonglong2*)&P[PS1 + 2 * i];
                ulonglong2 k0b = *(const ulonglong2*)&P[PS1 + 2 * i + 4];
                ulonglong2 k1a = *(const ulonglong2*)&P[PS1 + 128 + 2 * i];
                ulonglong2 k1b = *(const ulonglong2*)&P[PS1 + 128 + 2 * i + 4];
                ulonglong2 k2a = *(const ulonglong2*)&P[PS1 + 256 + 2 * i];
                ulonglong2 k2b = *(const ulonglong2*)&P[PS1 + 256 + 2 * i + 4];
                FMA4(O0[p], m0a, m0b, WA);
                FMA4(O1[p], k0a, k0b, WB);
                FMA4(O2[p], k1a, k1b, WB);
                FMA4(O3[p], k2a, k2b, WB);
            }
        }
        __syncwarp();   // done reading m0/m1 -> safe to overlay ob

        // ---- stage + coalesced store ----
#pragma unroll
        for (int p = 0; p < 2; p++) {
            float* obA = Sw + p * RS2 + PT1;
            float* obB = obA + 128;
            float xa, xb;
            upk2(O0[p], xa, xb); obA[lid] = xa;               obB[lid] = xb;
            upk2(O1[p], xa, xb); obA[32 + 3 * lid] = xa;      obB[32 + 3 * lid] = xb;
            upk2(O2[p], xa, xb); obA[33 + 3 * lid] = xa;      obB[33 + 3 * lid] = xb;
            upk2(O3[p], xa, xb); obA[34 + 3 * lid] = xa;      obB[34 + 3 * lid] = xb;
        }
        __syncwarp();
#pragma unroll
        for (int r = 0; r < 4; r++) {
            const float* ob = Sw + (r >> 1) * RS2 + PT1 + (r & 1) * 128;
            ((float4*)out)[(e + r) * 32 + lid] = *(const float4*)&ob[4 * lid];
        }
        __syncwarp();
    }
}

// ---------------- launch ----------------
extern "C" void kernel_launch(void* const* d_in, const int* in_sizes, int n_in,
                              void* d_out, int out_size) {
    const float* x1a     = (const float*)d_in[0];
    const float* x1b     = (const float*)d_in[1];
    const float* x2      = (const float*)d_in[2];
    const float* scalars = (const float*)d_in[3];
    const float* w0      = (const float*)d_in[4];
    const float* w1      = (const float*)d_in[5];
    const float* w2      = (const float*)d_in[6];
    const float* w3      = (const float*)d_in[7];
    const float* Wl0     = (const float*)d_in[8];
    const float* Wl1     = (const float*)d_in[9];
    const float* Wm1     = (const float*)d_in[10];
    const float* Wm2     = (const float*)d_in[11];
    const float* Wm3     = (const float*)d_in[12];
    const float* Wf0     = (const float*)d_in[13];
    const float* Wf1     = (const float*)d_in[14];
    int n = in_sizes[0] / 128;

    cudaFuncSetAttribute(tp_main_kernel, cudaFuncAttributeMaxDynamicSharedMemorySize, SMEM_BYTES);

    prep_kernel<<<112, 256>>>(w0, w1, w2, w3, Wl0, Wl1, Wm1, Wm2, Wm3, Wf0, Wf1);
    tp_main_kernel<<<148, 384, SMEM_BYTES>>>(x1a, x1b, (const float4*)x2, scalars,
                                             (float*)d_out, n);
}